// round 1
// baseline (speedup 1.0000x reference)
#include <cuda_runtime.h>
#include <cstdint>

// Problem constants
#define B_  2
#define C_  4
#define G_  128
#define T_  96

#define TILE 32
#define NTHR 256

// Channels-last template scratch: [B][z][y][x][C] as float4 per voxel.
// 2*96^3*4 floats = 28.3 MB
__device__ float4 g_tmpl_cl[(size_t)B_ * T_ * T_ * T_];

// ---------------------------------------------------------------------------
// Kernel 1: transpose template [B,C,T,T,T] -> channels-last float4 [B,T^3]
// ---------------------------------------------------------------------------
__global__ __launch_bounds__(256) void k_transpose_tmpl(const float* __restrict__ tmpl)
{
    const int TT3 = T_ * T_ * T_;
    int i = blockIdx.x * blockDim.x + threadIdx.x;   // over B*T^3
    if (i >= B_ * TT3) return;
    int b = i / TT3;
    int s = i - b * TT3;                              // z*T*T + y*T + x
    const float* p = tmpl + (size_t)b * C_ * TT3 + s;
    float4 v;
    v.x = __ldg(p);
    v.y = __ldg(p + (size_t)TT3);
    v.z = __ldg(p + (size_t)2 * TT3);
    v.w = __ldg(p + (size_t)3 * TT3);
    g_tmpl_cl[i] = v;
}

// ---------------------------------------------------------------------------
// Kernel 2: fused  defp-transpose + tanh + trilinear grid_sample + correction
//
// Tile: 32(d) x 32(w) at fixed (b,h). Shared-memory transpose keeps ALL
// global streams coalesced:
//   A-order (innermost w*3+c): grids read, defp write
//   B-order (innermost d):     deformation read, correction read, out write
// ---------------------------------------------------------------------------
__global__ __launch_bounds__(NTHR) void k_fused(
    const float* __restrict__ grids,     // [B,G,G,G,3]  (b,d,h,w,c)
    const float* __restrict__ defm,      // [B,3,G,G,G]  (b,c,w,h,d)
    const float* __restrict__ corr,      // [B,C,G,G,G]  (b,c,w,h,d)
    float*       __restrict__ out,       // [B,C,G,G,G]  (b,c,w,h,d)
    float*       __restrict__ defp)      // [B,G,G,G,3]  (b,d,h,w,c)
{
    // sdef[c][w][d]  (padded to kill bank conflicts)
    __shared__ float sdef[3][TILE][TILE + 1];
    // sfield[d][w*3+c], row stride 97 (odd -> conflict-free column access)
    __shared__ float sfield[TILE][TILE * 3 + 1];

    const int bz = blockIdx.z;
    const int b  = bz >> 7;          // bz / G_
    const int h  = bz & (G_ - 1);
    const int d0 = blockIdx.y * TILE;
    const int w0 = blockIdx.x * TILE;
    const int tid = threadIdx.x;

    // ---- Phase 1: load deformation tile, coalesced along d ----
    // defm offset(b,c,w,h,d) = (((b*3+c)*G + w)*G + h)*G + d
    #pragma unroll
    for (int i = tid; i < 3 * TILE * TILE; i += NTHR) {
        int c  = i / (TILE * TILE);
        int r  = i - c * (TILE * TILE);
        int w  = r >> 5;             // r / TILE
        int dl = r & (TILE - 1);
        size_t off = ((((size_t)b * 3 + c) * G_ + (w0 + w)) * G_ + h) * G_ + d0 + dl;
        sdef[c][w][dl] = defm[off];
    }
    __syncthreads();

    // ---- Phase 2: grids read + defp write + tanh, coalesced along (w,c) ----
    // grids/defp offset(b,d,h,w,c) = (((b*G+d)*G+h)*G + w)*3 + c
    #pragma unroll
    for (int i = tid; i < TILE * TILE * 3; i += NTHR) {
        int dl = i / (TILE * 3);
        int j  = i - dl * (TILE * 3);       // w*3 + c
        int w  = j / 3;
        int c  = j - w * 3;
        size_t off = ((((size_t)b * G_ + d0 + dl) * G_ + h) * G_ + w0) * 3 + j;
        float dv = sdef[c][w][dl];
        defp[off] = dv;
        float f = tanhf(__ldg(&grids[off]) + dv);
        sfield[dl][j] = f;
    }
    __syncthreads();

    // ---- Phase 3: trilinear gather + correction, coalesced along d ----
    const float4* tp = g_tmpl_cl + (size_t)b * T_ * T_ * T_;
    const float scale = 0.5f * (T_ - 1);

    #pragma unroll
    for (int i = tid; i < TILE * TILE; i += NTHR) {
        int dl = i & (TILE - 1);
        int w  = i >> 5;

        float fx = sfield[dl][w * 3 + 0];
        float fy = sfield[dl][w * 3 + 1];
        float fz = sfield[dl][w * 3 + 2];

        float ix = (fx + 1.0f) * scale;   // -> W (x index)
        float iy = (fy + 1.0f) * scale;   // -> H (y index)
        float iz = (fz + 1.0f) * scale;   // -> D (z index)

        float xf = floorf(ix), yf = floorf(iy), zf = floorf(iz);
        float wx = ix - xf, wy = iy - yf, wz = iz - zf;

        int x0 = min(max((int)xf, 0), T_ - 1); int x1 = min(x0 + 1, T_ - 1);
        int y0 = min(max((int)yf, 0), T_ - 1); int y1 = min(y0 + 1, T_ - 1);
        int z0 = min(max((int)zf, 0), T_ - 1); int z1 = min(z0 + 1, T_ - 1);

        int zy00 = (z0 * T_ + y0) * T_;
        int zy01 = (z0 * T_ + y1) * T_;
        int zy10 = (z1 * T_ + y0) * T_;
        int zy11 = (z1 * T_ + y1) * T_;

        float4 v000 = __ldg(&tp[zy00 + x0]);
        float4 v001 = __ldg(&tp[zy00 + x1]);
        float4 v010 = __ldg(&tp[zy01 + x0]);
        float4 v011 = __ldg(&tp[zy01 + x1]);
        float4 v100 = __ldg(&tp[zy10 + x0]);
        float4 v101 = __ldg(&tp[zy10 + x1]);
        float4 v110 = __ldg(&tp[zy11 + x0]);
        float4 v111 = __ldg(&tp[zy11 + x1]);

        // interpolate x, then y, then z (per channel)
        #define LERP(a, b, t) ((a) + ((b) - (a)) * (t))
        float4 c00, c01, c10, c11, c0v, c1v, r;
        c00.x = LERP(v000.x, v001.x, wx); c00.y = LERP(v000.y, v001.y, wx);
        c00.z = LERP(v000.z, v001.z, wx); c00.w = LERP(v000.w, v001.w, wx);
        c01.x = LERP(v010.x, v011.x, wx); c01.y = LERP(v010.y, v011.y, wx);
        c01.z = LERP(v010.z, v011.z, wx); c01.w = LERP(v010.w, v011.w, wx);
        c10.x = LERP(v100.x, v101.x, wx); c10.y = LERP(v100.y, v101.y, wx);
        c10.z = LERP(v100.z, v101.z, wx); c10.w = LERP(v100.w, v101.w, wx);
        c11.x = LERP(v110.x, v111.x, wx); c11.y = LERP(v110.y, v111.y, wx);
        c11.z = LERP(v110.z, v111.z, wx); c11.w = LERP(v110.w, v111.w, wx);
        c0v.x = LERP(c00.x, c01.x, wy); c0v.y = LERP(c00.y, c01.y, wy);
        c0v.z = LERP(c00.z, c01.z, wy); c0v.w = LERP(c00.w, c01.w, wy);
        c1v.x = LERP(c10.x, c11.x, wy); c1v.y = LERP(c10.y, c11.y, wy);
        c1v.z = LERP(c10.z, c11.z, wy); c1v.w = LERP(c10.w, c11.w, wy);
        r.x = LERP(c0v.x, c1v.x, wz); r.y = LERP(c0v.y, c1v.y, wz);
        r.z = LERP(c0v.z, c1v.z, wz); r.w = LERP(c0v.w, c1v.w, wz);
        #undef LERP

        // out/corr offset(b,c,w,h,d) = (((b*C+c)*G + w)*G + h)*G + d
        size_t ob = ((((size_t)b * C_ + 0) * G_ + (w0 + w)) * G_ + h) * G_ + d0 + dl;
        const size_t cs = (size_t)G_ * G_ * G_;
        out[ob]          = r.x + __ldg(&corr[ob]);
        out[ob + cs]     = r.y + __ldg(&corr[ob + cs]);
        out[ob + 2 * cs] = r.z + __ldg(&corr[ob + 2 * cs]);
        out[ob + 3 * cs] = r.w + __ldg(&corr[ob + 3 * cs]);
    }
}

// ---------------------------------------------------------------------------
extern "C" void kernel_launch(void* const* d_in, const int* in_sizes, int n_in,
                              void* d_out, int out_size)
{
    const float* grids = (const float*)d_in[0];  // 2*128^3*3
    const float* defm  = (const float*)d_in[1];  // 2*3*128^3
    const float* corr  = (const float*)d_in[2];  // 2*4*128^3
    const float* tmpl  = (const float*)d_in[3];  // 2*4*96^3

    float* out  = (float*)d_out;                              // 16,777,216 floats
    float* defp = out + (size_t)B_ * C_ * G_ * G_ * G_;       // 12,582,912 floats

    // 1) transpose template to channels-last
    {
        int n = B_ * T_ * T_ * T_;
        k_transpose_tmpl<<<(n + 255) / 256, 256>>>(tmpl);
    }
    // 2) fused main kernel
    {
        dim3 grid(G_ / TILE, G_ / TILE, B_ * G_);   // (w-tiles, d-tiles, b*h)
        k_fused<<<grid, NTHR>>>(grids, defm, corr, out, defp);
    }
}

// round 2
// speedup vs baseline: 1.1573x; 1.1573x over previous
#include <cuda_runtime.h>
#include <cuda_fp16.h>
#include <cstdint>

// Problem constants
#define B_  2
#define C_  4
#define G_  128
#define T_  96

#define TILE 32
#define NTHR 256

// Pair-duplicated channels-last fp16 template:
// entry[b][z][y][x] = { h(c0..c3 at x), h(c0..c3 at min(x+1,T-1)) }  (16 bytes)
// 2*96^3*16B = 28.3 MB
__device__ uint4 g_tmpl_ph[(size_t)B_ * T_ * T_ * T_];

// ---------------------------------------------------------------------------
// Kernel 1: build pair-duplicated fp16 template from [B,C,T,T,T] fp32
// ---------------------------------------------------------------------------
__global__ __launch_bounds__(256) void k_build_tmpl(const float* __restrict__ tmpl)
{
    const int TT3 = T_ * T_ * T_;
    int i = blockIdx.x * blockDim.x + threadIdx.x;   // over B*T^3
    if (i >= B_ * TT3) return;
    int b = i / TT3;
    int s = i - b * TT3;                              // z*T*T + y*T + x
    int x = s % T_;
    int sn = (x == T_ - 1) ? s : s + 1;               // clamped x+1

    const float* base = tmpl + (size_t)b * C_ * TT3;
    float a0 = __ldg(base + s);
    float a1 = __ldg(base + s + (size_t)TT3);
    float a2 = __ldg(base + s + (size_t)2 * TT3);
    float a3 = __ldg(base + s + (size_t)3 * TT3);
    float b0 = __ldg(base + sn);
    float b1 = __ldg(base + sn + (size_t)TT3);
    float b2 = __ldg(base + sn + (size_t)2 * TT3);
    float b3 = __ldg(base + sn + (size_t)3 * TT3);

    uint4 e;
    __half2 h;
    h = __floats2half2_rn(a0, a1); e.x = *reinterpret_cast<unsigned*>(&h);
    h = __floats2half2_rn(a2, a3); e.y = *reinterpret_cast<unsigned*>(&h);
    h = __floats2half2_rn(b0, b1); e.z = *reinterpret_cast<unsigned*>(&h);
    h = __floats2half2_rn(b2, b3); e.w = *reinterpret_cast<unsigned*>(&h);
    g_tmpl_ph[i] = e;
}

// x-lerp of one packed pair entry -> channels (0,1) and (2,3) as float2
__device__ __forceinline__ void lerpx(uint4 e, float wx, float2& r01, float2& r23)
{
    float2 a01 = __half22float2(*reinterpret_cast<__half2*>(&e.x));
    float2 a23 = __half22float2(*reinterpret_cast<__half2*>(&e.y));
    float2 b01 = __half22float2(*reinterpret_cast<__half2*>(&e.z));
    float2 b23 = __half22float2(*reinterpret_cast<__half2*>(&e.w));
    r01.x = fmaf(b01.x - a01.x, wx, a01.x);
    r01.y = fmaf(b01.y - a01.y, wx, a01.y);
    r23.x = fmaf(b23.x - a23.x, wx, a23.x);
    r23.y = fmaf(b23.y - a23.y, wx, a23.y);
}

// ---------------------------------------------------------------------------
// Kernel 2: fused  defp-transpose + tanh + trilinear grid_sample + correction
// Tile: 32(d) x 32(w) at fixed (b,h); shared-memory transpose keeps all
// global streams coalesced in both index orders.
// ---------------------------------------------------------------------------
__global__ __launch_bounds__(NTHR) void k_fused(
    const float* __restrict__ grids,     // [B,G,G,G,3]  (b,d,h,w,c)
    const float* __restrict__ defm,      // [B,3,G,G,G]  (b,c,w,h,d)
    const float* __restrict__ corr,      // [B,C,G,G,G]  (b,c,w,h,d)
    float*       __restrict__ out,       // [B,C,G,G,G]  (b,c,w,h,d)
    float*       __restrict__ defp)      // [B,G,G,G,3]  (b,d,h,w,c)
{
    __shared__ float sdef[3][TILE][TILE + 1];
    __shared__ float sfield[TILE][TILE * 3 + 1];   // row stride 97 (odd)

    const int bz = blockIdx.z;
    const int b  = bz >> 7;          // bz / G_
    const int h  = bz & (G_ - 1);
    const int d0 = blockIdx.y * TILE;
    const int w0 = blockIdx.x * TILE;
    const int tid = threadIdx.x;

    // ---- Phase 1: load deformation tile, coalesced along d ----
    #pragma unroll
    for (int i = tid; i < 3 * TILE * TILE; i += NTHR) {
        int c  = i / (TILE * TILE);
        int r  = i - c * (TILE * TILE);
        int w  = r >> 5;
        int dl = r & (TILE - 1);
        size_t off = ((((size_t)b * 3 + c) * G_ + (w0 + w)) * G_ + h) * G_ + d0 + dl;
        sdef[c][w][dl] = defm[off];
    }
    __syncthreads();

    // ---- Phase 2: grids read + defp write + tanh, coalesced along (w,c) ----
    #pragma unroll
    for (int i = tid; i < TILE * TILE * 3; i += NTHR) {
        int dl = i / (TILE * 3);
        int j  = i - dl * (TILE * 3);       // w*3 + c
        int w  = j / 3;
        int c  = j - w * 3;
        size_t off = ((((size_t)b * G_ + d0 + dl) * G_ + h) * G_ + w0) * 3 + j;
        float dv = sdef[c][w][dl];
        defp[off] = dv;
        sfield[dl][j] = tanhf(__ldg(&grids[off]) + dv);
    }
    __syncthreads();

    // ---- Phase 3: trilinear gather (4x LDG.128) + correction, coalesced along d
    const uint4* tp = g_tmpl_ph + (size_t)b * T_ * T_ * T_;
    const float scale = 0.5f * (T_ - 1);

    #pragma unroll
    for (int i = tid; i < TILE * TILE; i += NTHR) {
        int dl = i & (TILE - 1);
        int w  = i >> 5;

        float fx = sfield[dl][w * 3 + 0];
        float fy = sfield[dl][w * 3 + 1];
        float fz = sfield[dl][w * 3 + 2];

        float ix = (fx + 1.0f) * scale;
        float iy = (fy + 1.0f) * scale;
        float iz = (fz + 1.0f) * scale;

        float xf = floorf(ix), yf = floorf(iy), zf = floorf(iz);
        float wx = ix - xf, wy = iy - yf, wz = iz - zf;

        int x0 = min(max((int)xf, 0), T_ - 1);
        int y0 = min(max((int)yf, 0), T_ - 1); int y1 = min(y0 + 1, T_ - 1);
        int z0 = min(max((int)zf, 0), T_ - 1); int z1 = min(z0 + 1, T_ - 1);

        int zy00 = (z0 * T_ + y0) * T_ + x0;
        int zy01 = (z0 * T_ + y1) * T_ + x0;
        int zy10 = (z1 * T_ + y0) * T_ + x0;
        int zy11 = (z1 * T_ + y1) * T_ + x0;

        uint4 e00 = __ldg(&tp[zy00]);
        uint4 e01 = __ldg(&tp[zy01]);
        uint4 e10 = __ldg(&tp[zy10]);
        uint4 e11 = __ldg(&tp[zy11]);

        float2 c00a, c00b, c01a, c01b, c10a, c10b, c11a, c11b;
        lerpx(e00, wx, c00a, c00b);
        lerpx(e01, wx, c01a, c01b);
        lerpx(e10, wx, c10a, c10b);
        lerpx(e11, wx, c11a, c11b);

        // y-lerp
        float2 r0a, r0b, r1a, r1b;
        r0a.x = fmaf(c01a.x - c00a.x, wy, c00a.x);
        r0a.y = fmaf(c01a.y - c00a.y, wy, c00a.y);
        r0b.x = fmaf(c01b.x - c00b.x, wy, c00b.x);
        r0b.y = fmaf(c01b.y - c00b.y, wy, c00b.y);
        r1a.x = fmaf(c11a.x - c10a.x, wy, c10a.x);
        r1a.y = fmaf(c11a.y - c10a.y, wy, c10a.y);
        r1b.x = fmaf(c11b.x - c10b.x, wy, c10b.x);
        r1b.y = fmaf(c11b.y - c10b.y, wy, c10b.y);

        // z-lerp -> channels 0..3
        float o0 = fmaf(r1a.x - r0a.x, wz, r0a.x);
        float o1 = fmaf(r1a.y - r0a.y, wz, r0a.y);
        float o2 = fmaf(r1b.x - r0b.x, wz, r0b.x);
        float o3 = fmaf(r1b.y - r0b.y, wz, r0b.y);

        size_t ob = ((((size_t)b * C_ + 0) * G_ + (w0 + w)) * G_ + h) * G_ + d0 + dl;
        const size_t cs = (size_t)G_ * G_ * G_;
        out[ob]          = o0 + __ldg(&corr[ob]);
        out[ob + cs]     = o1 + __ldg(&corr[ob + cs]);
        out[ob + 2 * cs] = o2 + __ldg(&corr[ob + 2 * cs]);
        out[ob + 3 * cs] = o3 + __ldg(&corr[ob + 3 * cs]);
    }
}

// ---------------------------------------------------------------------------
extern "C" void kernel_launch(void* const* d_in, const int* in_sizes, int n_in,
                              void* d_out, int out_size)
{
    const float* grids = (const float*)d_in[0];  // 2*128^3*3
    const float* defm  = (const float*)d_in[1];  // 2*3*128^3
    const float* corr  = (const float*)d_in[2];  // 2*4*128^3
    const float* tmpl  = (const float*)d_in[3];  // 2*4*96^3

    float* out  = (float*)d_out;
    float* defp = out + (size_t)B_ * C_ * G_ * G_ * G_;

    {
        int n = B_ * T_ * T_ * T_;
        k_build_tmpl<<<(n + 255) / 256, 256>>>(tmpl);
    }
    {
        dim3 grid(G_ / TILE, G_ / TILE, B_ * G_);   // (w-tiles, d-tiles, b*h)
        k_fused<<<grid, NTHR>>>(grids, defm, corr, out, defp);
    }
}